// round 2
// baseline (speedup 1.0000x reference)
#include <cuda_runtime.h>
#include <cuda_bf16.h>
#include <math.h>

#define BS_   64
#define NQ_   300
#define T_    1280            // 64 * 20 targets
#define ROWS_ (BS_ * NQ_)     // 19200
#define RPB_  8               // rows per block
#define THREADS_ 320          // 1280 cols / 4 per thread

__device__ __forceinline__ float frcp(float x) {
    float r;
    asm("rcp.approx.f32 %0, %1;" : "=f"(r) : "f"(x));
    return r;
}

__global__ __launch_bounds__(THREADS_, 5)
void hungarian_cost_kernel(const float* __restrict__ logits,   // [ROWS_, 2]
                           const float* __restrict__ spans,    // [ROWS_, 2] (cx, w)
                           const float* __restrict__ tgt,      // [T_, 2]    (cx, w)
                           const float* __restrict__ refp,     // [ROWS_, 2]
                           float* __restrict__ out)            // [ROWS_, T_]
{
    // per-row constants packed as one float4: {cx, w, x1, rc1}
    __shared__ float4 s_row[RPB_];

    const int t    = threadIdx.x;          // owns columns 4t..4t+3
    const int row0 = blockIdx.x * RPB_;

    // ---- this thread's 4 target tuples, loaded once ----
    const float4 ta = __ldg(reinterpret_cast<const float4*>(tgt) + 2 * t);
    const float4 tb = __ldg(reinterpret_cast<const float4*>(tgt) + 2 * t + 1);

    float tcx[4], tw[4], tx1[4], tx2[4];
    tcx[0] = ta.x; tw[0] = ta.y;
    tcx[1] = ta.z; tw[1] = ta.w;
    tcx[2] = tb.x; tw[2] = tb.y;
    tcx[3] = tb.z; tw[3] = tb.w;
#pragma unroll
    for (int i = 0; i < 4; ++i) {
        tx1[i] = tcx[i] - 0.5f * tw[i];
        tx2[i] = tcx[i] + 0.5f * tw[i];
    }

    // ---- cooperative per-row constants (threads 0..RPB_-1) ----
    if (t < RPB_) {
        const int r = row0 + t;
        const float l0 = __ldg(logits + 2 * r);
        const float l1 = __ldg(logits + 2 * r + 1);
        const float m  = fmaxf(l0, l1);
        const float e0 = __expf(l0 - m);
        const float e1 = __expf(l1 - m);
        const float p0 = __fdividef(e0, e0 + e1);      // softmax prob class 0

        const float cx = __ldg(spans + 2 * r);
        const float w  = __ldg(spans + 2 * r + 1);
        const float x1 = cx - 0.5f * w;
        const float x2 = cx + 0.5f * w;

        const float r0 = __ldg(refp + 2 * r);
        const float r1 = __ldg(refp + 2 * r + 1);
        const float d0 = fabsf(x1 - r0);
        const float d1 = fabsf(x2 - r1);
        const float cref = sqrtf(fmaf(d0, d0, d1 * d1));

        // rc1 folds: cost_reference - cost_class_prob + the "+1" from
        //   -giou = 1 - inter/uni - uni/enc
        s_row[t] = make_float4(cx, w, x1, cref - p0 + 1.0f);
    }
    __syncthreads();

    // incremental store pointer: row0 * T_ + 4*t, advance T_ per row
    float4* op = reinterpret_cast<float4*>(out + (size_t)row0 * T_) + t;

    // ---- main loop: RPB_ rows, 4 columns each, one float4 store per row ----
#pragma unroll
    for (int rr = 0; rr < RPB_; ++rr) {
        const float4 rd = s_row[rr];
        const float cx  = rd.x;
        const float w   = rd.y;
        const float x1  = rd.z;
        const float rc1 = rd.w;
        const float x2  = x1 + w;

        float v[4];
#pragma unroll
        for (int i = 0; i < 4; ++i) {
            // L1 span cost + row constant (abs/neg are free operand modifiers)
            const float base  = fabsf(cx - tcx[i]) + fabsf(w - tw[i]) + rc1;
            // intersection / union / enclose (1D)
            const float lt    = fmaxf(x1, tx1[i]);
            const float rb    = fminf(x2, tx2[i]);
            const float inter = fmaxf(rb - lt, 0.0f);
            const float uni   = (w + tw[i]) - inter;
            const float enc   = fmaxf(x2, tx2[i]) - fminf(x1, tx1[i]);  // >= 0 always
            const float ru    = frcp(uni);
            const float re    = frcp(enc);
            // v = base - inter/uni - uni/enc   (== cspan - giou + cref - p0)
            float acc = fmaf(-inter, ru, base);
            v[i] = fmaf(-uni, re, acc);
        }

        *op = make_float4(v[0], v[1], v[2], v[3]);
        op += T_ / 4;
    }
}

extern "C" void kernel_launch(void* const* d_in, const int* in_sizes, int n_in,
                              void* d_out, int out_size) {
    const float* logits = (const float*)d_in[0];  // pred_logits [64,300,2]
    const float* spans  = (const float*)d_in[1];  // pred_spans  [64,300,2]
    const float* tgt    = (const float*)d_in[2];  // tgt_spans   [1280,2]
    const float* refp   = (const float*)d_in[3];  // ref_points  [64,300,2]
    float* out = (float*)d_out;                   // [64,300,1280] fp32

    const int blocks = ROWS_ / RPB_;              // 2400
    hungarian_cost_kernel<<<blocks, THREADS_>>>(logits, spans, tgt, refp, out);
}

// round 3
// speedup vs baseline: 1.0945x; 1.0945x over previous
#include <cuda_runtime.h>
#include <cuda_bf16.h>
#include <math.h>

#define BS_   64
#define NQ_   300
#define T_    1280            // 64 * 20 targets
#define ROWS_ (BS_ * NQ_)     // 19200
#define RPB_  16              // rows per block (R1 config — best so far)
#define THREADS_ 320          // 1280 cols / 4 per thread

__device__ __forceinline__ float frcp(float x) {
    float r;
    asm("rcp.approx.f32 %0, %1;" : "=f"(r) : "f"(x));
    return r;
}

__global__ __launch_bounds__(THREADS_, 4)
void hungarian_cost_kernel(const float* __restrict__ logits,   // [ROWS_, 2]
                           const float* __restrict__ spans,    // [ROWS_, 2] (cx, w)
                           const float* __restrict__ tgt,      // [T_, 2]    (cx, w)
                           const float* __restrict__ refp,     // [ROWS_, 2]
                           float* __restrict__ out)            // [ROWS_, T_]
{
    // per-row constants packed as one float4: {cx, w, x1, rc1}
    __shared__ float4 s_row[RPB_];

    const int t    = threadIdx.x;          // owns columns 4t..4t+3
    const int row0 = blockIdx.x * RPB_;

    // ---- this thread's 4 target tuples, loaded once, live in regs ----
    const float4 ta = __ldg(reinterpret_cast<const float4*>(tgt) + 2 * t);
    const float4 tb = __ldg(reinterpret_cast<const float4*>(tgt) + 2 * t + 1);

    float tcx[4], tw[4], tx1[4], tx2[4];
    tcx[0] = ta.x; tw[0] = ta.y;
    tcx[1] = ta.z; tw[1] = ta.w;
    tcx[2] = tb.x; tw[2] = tb.y;
    tcx[3] = tb.z; tw[3] = tb.w;
#pragma unroll
    for (int i = 0; i < 4; ++i) {
        tx1[i] = tcx[i] - 0.5f * tw[i];
        tx2[i] = tcx[i] + 0.5f * tw[i];
    }

    // ---- cooperative per-row constants (threads 0..RPB_-1) ----
    if (t < RPB_) {
        const int r = row0 + t;
        const float l0 = __ldg(logits + 2 * r);
        const float l1 = __ldg(logits + 2 * r + 1);
        const float m  = fmaxf(l0, l1);
        const float e0 = __expf(l0 - m);
        const float e1 = __expf(l1 - m);
        const float p0 = __fdividef(e0, e0 + e1);      // softmax prob class 0

        const float cx = __ldg(spans + 2 * r);
        const float w  = __ldg(spans + 2 * r + 1);
        const float x1 = cx - 0.5f * w;
        const float x2 = cx + 0.5f * w;

        const float r0 = __ldg(refp + 2 * r);
        const float r1 = __ldg(refp + 2 * r + 1);
        const float d0 = fabsf(x1 - r0);
        const float d1 = fabsf(x2 - r1);
        const float cref = sqrtf(fmaf(d0, d0, d1 * d1));

        // rc1 = cost_reference - class_prob + 1  (the +1 from -giou fold)
        s_row[t] = make_float4(cx, w, x1, cref - p0 + 1.0f);
    }
    __syncthreads();

    float4* op = reinterpret_cast<float4*>(out + (size_t)row0 * T_) + t;

    // ---- main loop: RPB_ rows, 4 columns each, one float4 store per row ----
#pragma unroll
    for (int rr = 0; rr < RPB_; ++rr) {
        const float4 rd = s_row[rr];
        const float cx  = rd.x;
        const float w   = rd.y;
        const float x1  = rd.z;
        const float rc1 = rd.w;
        const float x2  = x1 + w;

        float v[4];
#pragma unroll
        for (int i = 0; i < 4; ++i) {
            // L1 span cost + folded row constant (abs = free operand modifier)
            const float t0   = cx - tcx[i];
            const float t1   = w  - tw[i];
            const float base = (fabsf(t0) + fabsf(t1)) + rc1;
            // 1D GIoU via max+min=sum identity:
            //   enc = max(x2,tx2)-min(x1,tx1) = (w+tw) - (rb-lt)
            const float lt    = fmaxf(x1, tx1[i]);
            const float rb    = fminf(x2, tx2[i]);
            const float ri    = rb - lt;            // unclamped intersection
            const float s     = w + tw[i];
            const float inter = fmaxf(ri, 0.0f);
            const float uni   = s - inter;
            const float enc   = s - ri;
            const float ru    = frcp(uni);
            const float re    = frcp(enc);
            // v = base - inter/uni - uni/enc
            const float acc = fmaf(-inter, ru, base);
            v[i] = fmaf(-uni, re, acc);
        }

        *op = make_float4(v[0], v[1], v[2], v[3]);
        op += T_ / 4;
    }
}

extern "C" void kernel_launch(void* const* d_in, const int* in_sizes, int n_in,
                              void* d_out, int out_size) {
    const float* logits = (const float*)d_in[0];  // pred_logits [64,300,2]
    const float* spans  = (const float*)d_in[1];  // pred_spans  [64,300,2]
    const float* tgt    = (const float*)d_in[2];  // tgt_spans   [1280,2]
    const float* refp   = (const float*)d_in[3];  // ref_points  [64,300,2]
    float* out = (float*)d_out;                   // [64,300,1280] fp32

    const int blocks = ROWS_ / RPB_;              // 1200
    hungarian_cost_kernel<<<blocks, THREADS_>>>(logits, spans, tgt, refp, out);
}